// round 1
// baseline (speedup 1.0000x reference)
#include <cuda_runtime.h>
#include <cstdint>
#include <math.h>

#define B   2
#define NS  512
#define H   768
#define C   108
#define D   64
#define PIX (NS*NS)       // 262144
#define CH_HID 6

// ---------------- device scratch (no allocations allowed) ----------------
__device__ float    g_qw[B*NS*D];
__device__ float    g_kw[B*NS*D];
__device__ float    g_ev[C*D];
__device__ float    g_chanSum[B*C];
__device__ unsigned g_chanMaxKey[B*C];
__device__ float    g_scale[B*C];
__device__ float    g_compMax[B*PIX];
__device__ float    g_compMean[B*PIX];
__device__ float    g_sig[B*PIX];

// order-preserving float->uint key for atomicMax on signed floats
__device__ __forceinline__ unsigned fkey(float f){
    unsigned u = __float_as_uint(f);
    return (u & 0x80000000u) ? ~u : (u | 0x80000000u);
}
__device__ __forceinline__ float fkeyinv(unsigned k){
    return __uint_as_float((k & 0x80000000u) ? (k & 0x7fffffffu) : ~k);
}

// packed fp32x2 helpers (Blackwell f32x2 pipe)
__device__ __forceinline__ unsigned long long fma2(unsigned long long a, unsigned long long b, unsigned long long c){
    unsigned long long d;
    asm("fma.rn.f32x2 %0, %1, %2, %3;" : "=l"(d) : "l"(a), "l"(b), "l"(c));
    return d;
}
__device__ __forceinline__ unsigned long long pack2(float lo, float hi){
    unsigned long long d; asm("mov.b64 %0, {%1, %2};" : "=l"(d) : "f"(lo), "f"(hi)); return d;
}
__device__ __forceinline__ float sum2(unsigned long long a){
    float lo, hi; asm("mov.b64 {%0, %1}, %2;" : "=f"(lo), "=f"(hi) : "l"(a)); return lo + hi;
}

// ---------------- K0: init stats ----------------
__global__ void k0_init(){
    int i = threadIdx.x;
    if (i < B*C){ g_chanSum[i] = 0.f; g_chanMaxKey[i] = 0u; }
}

// ---------------- K1: seq = inputs@w_dense + b_dense, then RoPE -> qw, kw ----------------
#define K1_M 8
__global__ __launch_bounds__(128) void k1_qk(const float* __restrict__ inp,
                                             const float* __restrict__ wd,
                                             const float* __restrict__ bd){
    __shared__ float in_s[K1_M][H];     // 24 KB
    __shared__ float seq_s[K1_M][128];  // 4 KB
    const int b = blockIdx.y, m0 = blockIdx.x * K1_M, tid = threadIdx.x;

    const float* src = inp + ((size_t)b*NS + m0) * H;
    for (int i = tid; i < K1_M*H; i += 128) in_s[i/H][i%H] = src[i];
    __syncthreads();

    const int col = tid;
    float acc[K1_M];
#pragma unroll
    for (int mi = 0; mi < K1_M; mi++) acc[mi] = 0.f;

#pragma unroll 1
    for (int h = 0; h < H; h += 4){
        float w0 = wd[(h+0)*128 + col];
        float w1 = wd[(h+1)*128 + col];
        float w2 = wd[(h+2)*128 + col];
        float w3 = wd[(h+3)*128 + col];
#pragma unroll
        for (int mi = 0; mi < K1_M; mi++){
            float4 iv = *reinterpret_cast<const float4*>(&in_s[mi][h]);
            acc[mi] = fmaf(iv.x, w0, acc[mi]);
            acc[mi] = fmaf(iv.y, w1, acc[mi]);
            acc[mi] = fmaf(iv.z, w2, acc[mi]);
            acc[mi] = fmaf(iv.w, w3, acc[mi]);
        }
    }
    const float bb = bd[col];
#pragma unroll
    for (int mi = 0; mi < K1_M; mi++) seq_s[mi][col] = acc[mi] + bb;
    __syncthreads();

    // RoPE: pair tasks. accurate trig via double (immune to fast-math)
    for (int t = tid; t < K1_M*64; t += 128){
        int mi = t >> 6;
        int p  = t & 63;
        int which = p >> 5;        // 0 -> q, 1 -> k
        int j = p & 31;
        int m = m0 + mi;
        // div = exp(2j * (-ln(10000)/64)) ; -2*ln(1e4)/64 = -0.28782313662425574
        float divf = (float)exp((double)j * -0.28782313662425574);
        float ang  = (float)m * divf;          // matches ref fp32 rounding
        double ad  = (double)ang;
        float cv = (float)cos(ad);
        float sv = (float)sin(ad);
        int base = which*64 + 2*j;
        float x0 = seq_s[mi][base], x1 = seq_s[mi][base+1];
        float r0 = x0*cv - x1*sv;
        float r1 = x1*cv + x0*sv;
        float* dst = which ? g_kw : g_qw;
        size_t o = ((size_t)b*NS + m) * D + 2*j;
        dst[o]   = r0;
        dst[o+1] = r1;
    }
}

// ---------------- K1b: ev = event_inputs@w_event + b_event ----------------
__global__ __launch_bounds__(64) void k1b_ev(const float* __restrict__ ein,
                                             const float* __restrict__ we,
                                             const float* __restrict__ be){
    __shared__ float e_s[H];
    const int c = blockIdx.x, tid = threadIdx.x;
    for (int i = tid; i < H; i += 64) e_s[i] = ein[(size_t)c*H + i];
    __syncthreads();
    float acc = 0.f;
#pragma unroll 1
    for (int h = 0; h < H; h += 4){
        float4 ev4 = *reinterpret_cast<const float4*>(&e_s[h]);
        acc = fmaf(ev4.x, we[(h+0)*D + tid], acc);
        acc = fmaf(ev4.y, we[(h+1)*D + tid], acc);
        acc = fmaf(ev4.z, we[(h+2)*D + tid], acc);
        acc = fmaf(ev4.w, we[(h+3)*D + tid], acc);
    }
    g_ev[c*D + tid] = acc + be[tid];
}

// ---------------- K2: x[b,c,m,n] = sum_d q*k*ev ; write to out ; channel stats ----------------
#define BM 8
#define BN 32
__global__ __launch_bounds__(256) void k2_einsum(float* __restrict__ out){
    __shared__ float q_s[BM][D];                 // 2 KB
    __shared__ float k_s[BN][D+1];               // 8.3 KB (pad: conflict-free)
    __shared__ __align__(16) float ev_s[C*D];    // 27.6 KB
    __shared__ float qs_s[D], ks_s[D];
    __shared__ unsigned cmax_s[C];

    const int tid = threadIdx.x;
    const int b  = blockIdx.z;
    const int m0 = blockIdx.y * BM;
    const int n0 = blockIdx.x * BN;

    for (int i = tid; i < BM*D; i += 256) q_s[i>>6][i&63] = g_qw[((size_t)b*NS + m0)*D + i];
    for (int i = tid; i < BN*D; i += 256) k_s[i>>6][i&63] = g_kw[((size_t)b*NS + n0)*D + i];
    for (int i = tid; i < C*D/4; i += 256)
        reinterpret_cast<float4*>(ev_s)[i] = reinterpret_cast<const float4*>(g_ev)[i];
    for (int i = tid; i < C; i += 256) cmax_s[i] = 0u;
    __syncthreads();

    // factorized per-block channel-sum helpers: sum_px t[d] = (sum_m q)(sum_n k)
    if (tid < D){
        float qs = 0.f, ks = 0.f;
#pragma unroll
        for (int mi = 0; mi < BM; mi++) qs += q_s[mi][tid];
#pragma unroll
        for (int ni = 0; ni < BN; ni++) ks += k_s[ni][tid];
        qs_s[tid] = qs; ks_s[tid] = ks;
    }

    const int mi = tid >> 5, ni = tid & 31;
    unsigned long long t2[32];
#pragma unroll
    for (int j = 0; j < 32; j++){
        float lo = q_s[mi][2*j]   * k_s[ni][2*j];
        float hi = q_s[mi][2*j+1] * k_s[ni][2*j+1];
        t2[j] = pack2(lo, hi);
    }

    const size_t obase = (size_t)b*C*PIX + (size_t)(m0+mi)*NS + (n0+ni);
#pragma unroll 1
    for (int c = 0; c < C; c++){
        const ulonglong2* ev2 = reinterpret_cast<const ulonglong2*>(ev_s + c*D);
        unsigned long long a0 = 0ull, a1 = 0ull;
#pragma unroll
        for (int j = 0; j < 16; j++){
            ulonglong2 e = ev2[j];
            a0 = fma2(e.x, t2[2*j],   a0);
            a1 = fma2(e.y, t2[2*j+1], a1);
        }
        float acc = sum2(a0) + sum2(a1);
        out[obase + (size_t)c*PIX] = acc;

        // channel max: warp reduce + smem atomic
        float wm = acc;
#pragma unroll
        for (int off = 16; off > 0; off >>= 1)
            wm = fmaxf(wm, __shfl_xor_sync(0xffffffffu, wm, off));
        if (ni == 0) atomicMax(&cmax_s[c], fkey(wm));
    }
    __syncthreads();

    // per-block channel sums (factorized, exact in real arithmetic) + global commit
    for (int c = tid; c < C; c += 256){
        float s = 0.f;
#pragma unroll 1
        for (int d = 0; d < D; d++) s = fmaf(ev_s[c*D + d], qs_s[d]*ks_s[d], s);
        atomicAdd(&g_chanSum[b*C + c], s);
        atomicMax(&g_chanMaxKey[b*C + c], cmax_s[c]);
    }
}

// ---------------- K3: channel-attention scale = sigmoid(mlp(avg)+mlp(max)) ----------------
__global__ __launch_bounds__(128) void k3_scale(const float* __restrict__ w1, const float* __restrict__ b1,
                                                const float* __restrict__ w2, const float* __restrict__ b2){
    __shared__ float avg_s[C], mx_s[C], hid_s[12];
    const int tid = threadIdx.x;
    for (int b = 0; b < B; b++){
        if (tid < C){
            avg_s[tid] = g_chanSum[b*C + tid] * (1.f/262144.f);
            mx_s[tid]  = fkeyinv(g_chanMaxKey[b*C + tid]);
        }
        __syncthreads();
        if (tid < 12){
            int which = tid / 6, j = tid % 6;
            const float* v = which ? mx_s : avg_s;
            float h = b1[j];
            for (int c2 = 0; c2 < C; c2++) h = fmaf(v[c2], w1[c2*CH_HID + j], h);
            hid_s[tid] = fmaxf(h, 0.f);
        }
        __syncthreads();
        if (tid < C){
            float z = 2.f * b2[tid];   // b2 added in each mlp branch
            for (int j = 0; j < CH_HID; j++)
                z = fmaf(hid_s[j] + hid_s[6+j], w2[j*C + tid], z);
            g_scale[b*C + tid] = 1.f / (1.f + expf(-z));
        }
        __syncthreads();
    }
}

// ---------------- K4: comp = [max_c, mean_c] of x*scale ----------------
__global__ __launch_bounds__(128) void k4_comp(const float* __restrict__ x){
    __shared__ float sc_s[C];
    const int b = blockIdx.y, m = blockIdx.x, tid = threadIdx.x;
    if (tid < C) sc_s[tid] = g_scale[b*C + tid];
    __syncthreads();

    const float4* base = reinterpret_cast<const float4*>(x) + ((size_t)b*C*PIX + (size_t)m*NS)/4;
    float4 mx = make_float4(-3.402823466e38f, -3.402823466e38f, -3.402823466e38f, -3.402823466e38f);
    float4 sm = make_float4(0.f, 0.f, 0.f, 0.f);
#pragma unroll 4
    for (int c = 0; c < C; c++){
        float4 v = __ldg(base + (size_t)c*(PIX/4) + tid);
        float s = sc_s[c];
        float a = v.x*s, bb = v.y*s, cc = v.z*s, dd = v.w*s;
        mx.x = fmaxf(mx.x, a); mx.y = fmaxf(mx.y, bb); mx.z = fmaxf(mx.z, cc); mx.w = fmaxf(mx.w, dd);
        sm.x += a; sm.y += bb; sm.z += cc; sm.w += dd;
    }
    const float inv = 1.f / 108.f;
    sm.x *= inv; sm.y *= inv; sm.z *= inv; sm.w *= inv;
    const int po = (b*NS + m)*128 + tid;
    reinterpret_cast<float4*>(g_compMax)[po]  = mx;
    reinterpret_cast<float4*>(g_compMean)[po] = sm;
}

// ---------------- K5: 7x7 conv (2->1) + BN-sqrt + sigmoid ----------------
#define CT 16
__global__ __launch_bounds__(256) void k5_conv(const float* __restrict__ cw){
    __shared__ float smax[CT+6][CT+6];
    __shared__ float smean[CT+6][CT+6];
    __shared__ float w_s[98];
    const int b = blockIdx.z, m0 = blockIdx.y*CT, n0 = blockIdx.x*CT, tid = threadIdx.x;
    if (tid < 98) w_s[tid] = cw[tid];
    for (int i = tid; i < (CT+6)*(CT+6); i += 256){
        int r = i / (CT+6), cc = i % (CT+6);
        int gm = m0 + r - 3, gn = n0 + cc - 3;
        float a = 0.f, mn = 0.f;
        if (gm >= 0 && gm < NS && gn >= 0 && gn < NS){
            size_t gi = (size_t)(b*NS + gm)*NS + gn;
            a  = g_compMax[gi];
            mn = g_compMean[gi];
        }
        smax[r][cc] = a; smean[r][cc] = mn;
    }
    __syncthreads();
    const int ty = tid / CT, tx = tid % CT;
    float acc = 0.f;
#pragma unroll
    for (int kh = 0; kh < 7; kh++)
#pragma unroll
        for (int kw = 0; kw < 7; kw++){
            acc = fmaf(smax[ty+kh][tx+kw],  w_s[kh*7 + kw],      acc);
            acc = fmaf(smean[ty+kh][tx+kw], w_s[49 + kh*7 + kw], acc);
        }
    acc *= 0.9999950000374997f;  // 1/sqrt(1+1e-5)
    g_sig[(size_t)(b*NS + m0 + ty)*NS + n0 + tx] = 1.f / (1.f + expf(-acc));
}

// ---------------- K6: out = (x*(scale*sig+1) [mask] - tril*1e12) / 8 ----------------
__global__ __launch_bounds__(256) void k6_final(float* __restrict__ out, const int* __restrict__ mask){
    const int idx4 = blockIdx.x*256 + threadIdx.x;   // float4 index, total 14155776
    const int nq = idx4 & 127;
    const int m  = (idx4 >> 7) & 511;
    const int bc = idx4 >> 16;           // 0..215
    const int b  = (bc >= C) ? 1 : 0;

    float4 x  = reinterpret_cast<float4*>(out)[idx4];
    const float sc = g_scale[bc];
    float4 sg = reinterpret_cast<const float4*>(g_sig)[(b*NS + m)*128 + nq];

    const int mr = mask[b*NS + m];
    const int n0 = nq*4;
    const int* mcol = mask + b*NS + n0;
    const float NEGINF = __int_as_float(0xff800000);

    float xs[4]  = {x.x, x.y, x.z, x.w};
    float sgv[4] = {sg.x, sg.y, sg.z, sg.w};
    float r[4];
#pragma unroll
    for (int i = 0; i < 4; i++){
        float y = xs[i] * fmaf(sc, sgv[i], 1.f);
        if (m > n0 + i) y -= 1e12f;
        if (mr == 0 || mcol[i] == 0) y = NEGINF;
        r[i] = y * 0.125f;
    }
    reinterpret_cast<float4*>(out)[idx4] = make_float4(r[0], r[1], r[2], r[3]);
}

// ---------------- launcher ----------------
extern "C" void kernel_launch(void* const* d_in, const int* in_sizes, int n_in,
                              void* d_out, int out_size){
    (void)in_sizes; (void)n_in; (void)out_size;
    const float* inputs       = (const float*)d_in[0];
    const float* event_inputs = (const float*)d_in[1];
    const int*   mask         = (const int*)  d_in[2];
    const float* w_dense      = (const float*)d_in[3];
    const float* b_dense      = (const float*)d_in[4];
    const float* w_event      = (const float*)d_in[5];
    const float* b_event      = (const float*)d_in[6];
    const float* mlp_w1       = (const float*)d_in[7];
    const float* mlp_b1       = (const float*)d_in[8];
    const float* mlp_w2       = (const float*)d_in[9];
    const float* mlp_b2       = (const float*)d_in[10];
    const float* conv_w       = (const float*)d_in[11];
    float* out = (float*)d_out;

    k0_init<<<1, 256>>>();
    k1_qk<<<dim3(64, 2), 128>>>(inputs, w_dense, b_dense);
    k1b_ev<<<108, 64>>>(event_inputs, w_event, b_event);
    k2_einsum<<<dim3(16, 64, 2), 256>>>(out);
    k3_scale<<<1, 128>>>(mlp_w1, mlp_b1, mlp_w2, mlp_b2);
    k4_comp<<<dim3(512, 2), 128>>>(out);
    k5_conv<<<dim3(32, 32, 2), 256>>>(conv_w);
    k6_final<<<55296, 256>>>(out, mask);
}

// round 7
// speedup vs baseline: 1.6164x; 1.6164x over previous
#include <cuda_runtime.h>
#include <cuda_bf16.h>
#include <cstdint>
#include <math.h>

#define B   2
#define NS  512
#define H   768
#define C   108
#define D   64
#define PIX (NS*NS)
#define CH_HID 6
#define MROWS (C*NS)        // 55296 rows per batch in GEMM formulation

// ---------------- device scratch ----------------
__device__ float          g_qw[B*NS*D];
__device__ float          g_kw[B*NS*D];
__device__ float          g_ev[C*D];
__device__ float          g_Qs[B*D];
__device__ float          g_Ks[B*D];
__device__ unsigned       g_chanMaxKey[B*C];
__device__ float          g_scale[B*C];
__device__ float          g_compMax[B*PIX];
__device__ float          g_compMean[B*PIX];
__device__ float          g_sig[B*PIX];
__device__ __nv_bfloat16  g_A[B*MROWS*D];     // 14.2 MB: bf16(ev*q)
__device__ __nv_bfloat16  g_Kb[B*NS*D];       // bf16(k)

__device__ __forceinline__ unsigned fkey(float f){
    unsigned u = __float_as_uint(f);
    return (u & 0x80000000u) ? ~u : (u | 0x80000000u);
}
__device__ __forceinline__ float fkeyinv(unsigned k){
    return __uint_as_float((k & 0x80000000u) ? (k & 0x7fffffffu) : ~k);
}

__device__ __forceinline__ uint32_t smem_u32(const void* p){
    uint32_t a;
    asm("{ .reg .u64 t; cvta.to.shared.u64 t, %1; cvt.u32.u64 %0, t; }" : "=r"(a) : "l"(p));
    return a;
}
__device__ __forceinline__ uint32_t swz128(uint32_t off){ return off ^ ((off >> 3) & 0x70); }

// ---- warp-level bf16 tensor core ops (baseline PTX, works on .target sm_100) ----
__device__ __forceinline__ void ldm_x4(uint32_t* r, uint32_t addr){
    asm volatile("ldmatrix.sync.aligned.m8n8.x4.shared.b16 {%0,%1,%2,%3}, [%4];"
        : "=r"(r[0]), "=r"(r[1]), "=r"(r[2]), "=r"(r[3]) : "r"(addr));
}
__device__ __forceinline__ void ldm_x2(uint32_t* r, uint32_t addr){
    asm volatile("ldmatrix.sync.aligned.m8n8.x2.shared.b16 {%0,%1}, [%2];"
        : "=r"(r[0]), "=r"(r[1]) : "r"(addr));
}
__device__ __forceinline__ void mma16816(float* c, const uint32_t* a, const uint32_t* b){
    asm volatile("mma.sync.aligned.m16n8k16.row.col.f32.bf16.bf16.f32 "
        "{%0,%1,%2,%3}, {%4,%5,%6,%7}, {%8,%9}, {%0,%1,%2,%3};"
        : "+f"(c[0]), "+f"(c[1]), "+f"(c[2]), "+f"(c[3])
        : "r"(a[0]), "r"(a[1]), "r"(a[2]), "r"(a[3]), "r"(b[0]), "r"(b[1]));
}

// ---------------- K0: init stats ----------------
__global__ void k0_init(){
    int i = threadIdx.x;
    if (i < B*C) g_chanMaxKey[i] = 0u;
}

// ---------------- K1: dense + RoPE -> qw, kw (fp32) ----------------
#define K1_M 8
__global__ __launch_bounds__(128) void k1_qk(const float* __restrict__ inp,
                                             const float* __restrict__ wd,
                                             const float* __restrict__ bd){
    __shared__ float in_s[K1_M][H];
    __shared__ float seq_s[K1_M][128];
    const int b = blockIdx.y, m0 = blockIdx.x * K1_M, tid = threadIdx.x;

    const float* src = inp + ((size_t)b*NS + m0) * H;
    for (int i = tid; i < K1_M*H; i += 128) in_s[i/H][i%H] = src[i];
    __syncthreads();

    const int col = tid;
    float acc[K1_M];
#pragma unroll
    for (int mi = 0; mi < K1_M; mi++) acc[mi] = 0.f;
#pragma unroll 1
    for (int h = 0; h < H; h += 4){
        float w0 = wd[(h+0)*128 + col];
        float w1 = wd[(h+1)*128 + col];
        float w2 = wd[(h+2)*128 + col];
        float w3 = wd[(h+3)*128 + col];
#pragma unroll
        for (int mi = 0; mi < K1_M; mi++){
            float4 iv = *reinterpret_cast<const float4*>(&in_s[mi][h]);
            acc[mi] = fmaf(iv.x, w0, acc[mi]);
            acc[mi] = fmaf(iv.y, w1, acc[mi]);
            acc[mi] = fmaf(iv.z, w2, acc[mi]);
            acc[mi] = fmaf(iv.w, w3, acc[mi]);
        }
    }
    const float bb = bd[col];
#pragma unroll
    for (int mi = 0; mi < K1_M; mi++) seq_s[mi][col] = acc[mi] + bb;
    __syncthreads();

    for (int t = tid; t < K1_M*64; t += 128){
        int mi = t >> 6, p = t & 63;
        int which = p >> 5, j = p & 31;
        int m = m0 + mi;
        float divf = (float)exp((double)j * -0.28782313662425574);
        float ang  = (float)m * divf;
        double ad  = (double)ang;
        float cv = (float)cos(ad), sv = (float)sin(ad);
        int base = which*64 + 2*j;
        float x0 = seq_s[mi][base], x1 = seq_s[mi][base+1];
        float* dst = which ? g_kw : g_qw;
        size_t o = ((size_t)b*NS + m) * D + 2*j;
        dst[o]   = x0*cv - x1*sv;
        dst[o+1] = x1*cv + x0*sv;
    }
}

// ---------------- K1b: ev ----------------
__global__ __launch_bounds__(64) void k1b_ev(const float* __restrict__ ein,
                                             const float* __restrict__ we,
                                             const float* __restrict__ be){
    __shared__ float e_s[H];
    const int c = blockIdx.x, tid = threadIdx.x;
    for (int i = tid; i < H; i += 64) e_s[i] = ein[(size_t)c*H + i];
    __syncthreads();
    float acc = 0.f;
#pragma unroll 1
    for (int h = 0; h < H; h += 4){
        float4 ev4 = *reinterpret_cast<const float4*>(&e_s[h]);
        acc = fmaf(ev4.x, we[(h+0)*D + tid], acc);
        acc = fmaf(ev4.y, we[(h+1)*D + tid], acc);
        acc = fmaf(ev4.z, we[(h+2)*D + tid], acc);
        acc = fmaf(ev4.w, we[(h+3)*D + tid], acc);
    }
    g_ev[c*D + tid] = acc + be[tid];
}

// ---------------- Ksum: Qs[b][d] = sum_m q ; Ks = sum_n k ----------------
__global__ __launch_bounds__(64) void k_sum(){
    const int b = blockIdx.x >> 1, which = blockIdx.x & 1, d = threadIdx.x;
    const float* src = (which ? g_kw : g_qw) + (size_t)b*NS*D + d;
    float s = 0.f;
#pragma unroll 8
    for (int m = 0; m < NS; m++) s += src[(size_t)m*D];
    (which ? g_Ks : g_Qs)[b*D + d] = s;
}

// ---------------- K15a: A[(c,m),d] = bf16(ev*q) ----------------
__global__ __launch_bounds__(256) void k15_A(){
    __shared__ float ev_s[D];
    const int bid = blockIdx.x;           // 0..863
    const int b = bid / 432, t = bid % 432;
    const int c = t >> 2, m0 = (t & 3) * 128;
    const int tid = threadIdx.x;
    if (tid < D) ev_s[tid] = g_ev[c*D + tid];
    __syncthreads();
    const float* q = g_qw + ((size_t)b*NS + m0)*D;
    __nv_bfloat16* dst = g_A + ((size_t)b*MROWS + (size_t)c*NS + m0)*D;
    for (int i = tid; i < 128*D; i += 256){
        int d = i & 63;
        dst[i] = __float2bfloat16(ev_s[d] * q[i]);
    }
}

// ---------------- K15b: Kb = bf16(kw) ----------------
__global__ __launch_bounds__(256) void k15_Kb(){
    int idx = blockIdx.x*256 + threadIdx.x;   // 65536 total
    g_Kb[idx] = __float2bfloat16(g_kw[idx]);
}

// ---------------- K2: warp-mma bf16 GEMM; epilogue: store x + channel max ----------------
// block tile M=128 (rows of one channel) x N=128, K=64. 8 warps (2x4), warp tile 64x32.
#define TN 128
__global__ __launch_bounds__(256) void k2_mma(float* __restrict__ out){
    __shared__ __align__(1024) char smem[32768];   // A 16KB @0, B 16KB @16384
    __shared__ float red_s[8];
    const uint32_t sbA = smem_u32(smem);
    const uint32_t sbB = sbA + 16384;

    const int tid = threadIdx.x;
    const int wid = tid >> 5, lane = tid & 31;
    const int warp_m = wid >> 2;          // 0..1 (64 rows each)
    const int warp_n = wid & 3;           // 0..3 (32 cols each)

    const int b   = blockIdx.z;
    const int rt  = blockIdx.y;           // 0..431
    const int n0  = blockIdx.x * TN;
    const int c   = rt >> 2;
    const int m0  = (rt & 3) * 128;

    // ---- load A and B tiles into swizzled smem (128 rows x 128B each) ----
    {
        const uint4* pA = reinterpret_cast<const uint4*>(g_A);
        const size_t abase = ((size_t)b*MROWS + (size_t)c*NS + m0) * 8;   // 8 uint4 per 64-bf16 row
        const uint4* pB = reinterpret_cast<const uint4*>(g_Kb);
        const size_t bbase = ((size_t)b*NS + n0) * 8;
#pragma unroll
        for (int it = 0; it < 4; it++){
            int i = it*256 + tid;              // 0..1023
            int row = i >> 3, c16 = i & 7;
            uint32_t so = swz128(row*128 + c16*16);
            *reinterpret_cast<uint4*>(smem + so)         = pA[abase + (size_t)row*8 + c16];
            *reinterpret_cast<uint4*>(smem + 16384 + so) = pB[bbase + (size_t)row*8 + c16];
        }
    }
    __syncthreads();

    // ---- mainloop: K=64 in 4 chunks of 16 ----
    float acc[4][4][4];
#pragma unroll
    for (int i = 0; i < 4; i++)
#pragma unroll
        for (int j = 0; j < 4; j++)
#pragma unroll
            for (int r = 0; r < 4; r++) acc[i][j][r] = 0.f;

#pragma unroll
    for (int kt = 0; kt < 4; kt++){
        uint32_t af[4][4], bf[4][2];
        // A fragments: m16k16 from row-major [m][k] -> ldmatrix x4 (non-trans)
#pragma unroll
        for (int i = 0; i < 4; i++){
            int row = warp_m*64 + i*16 + (lane & 15);
            uint32_t off = swz128(row*128 + kt*32 + (lane >> 4)*16);
            ldm_x4(af[i], sbA + off);
        }
        // B fragments: n8k16 from row-major [n][k] -> ldmatrix x2 (non-trans)
#pragma unroll
        for (int j = 0; j < 4; j++){
            int row = warp_n*32 + j*8 + (lane & 7);
            uint32_t off = swz128(row*128 + kt*32 + ((lane >> 3) & 1)*16);
            ldm_x2(bf[j], sbB + off);
        }
#pragma unroll
        for (int i = 0; i < 4; i++)
#pragma unroll
            for (int j = 0; j < 4; j++)
                mma16816(acc[i][j], af[i], bf[j]);
    }

    // ---- epilogue: direct coalesced stores + fused channel max ----
    const size_t obase = ((size_t)(b*C + c)*NS + m0)*NS + n0;
    float mx = -3.402823466e38f;
#pragma unroll
    for (int i = 0; i < 4; i++){
        int row0 = warp_m*64 + i*16 + (lane >> 2);
#pragma unroll
        for (int j = 0; j < 4; j++){
            int col = warp_n*32 + j*8 + (lane & 3)*2;
            float c0 = acc[i][j][0], c1 = acc[i][j][1];
            float c2 = acc[i][j][2], c3 = acc[i][j][3];
            mx = fmaxf(mx, fmaxf(fmaxf(c0, c1), fmaxf(c2, c3)));
            *reinterpret_cast<float2*>(&out[obase + (size_t)row0*NS + col])     = make_float2(c0, c1);
            *reinterpret_cast<float2*>(&out[obase + (size_t)(row0+8)*NS + col]) = make_float2(c2, c3);
        }
    }
#pragma unroll
    for (int off = 16; off > 0; off >>= 1)
        mx = fmaxf(mx, __shfl_xor_sync(0xffffffffu, mx, off));
    if (lane == 0) red_s[wid] = mx;
    __syncthreads();
    if (tid == 0){
        float m2 = red_s[0];
#pragma unroll
        for (int w = 1; w < 8; w++) m2 = fmaxf(m2, red_s[w]);
        atomicMax(&g_chanMaxKey[b*C + c], fkey(m2));
    }
}

// ---------------- K3: scale ----------------
__global__ __launch_bounds__(128) void k3_scale(const float* __restrict__ w1, const float* __restrict__ b1,
                                                const float* __restrict__ w2, const float* __restrict__ b2){
    __shared__ float avg_s[C], mx_s[C], hid_s[12];
    const int tid = threadIdx.x;
    for (int b = 0; b < B; b++){
        if (tid < C){
            float s = 0.f;
            for (int d = 0; d < D; d++)
                s = fmaf(g_ev[tid*D + d], g_Qs[b*D + d]*g_Ks[b*D + d], s);
            avg_s[tid] = s * (1.f/262144.f);
            mx_s[tid]  = fkeyinv(g_chanMaxKey[b*C + tid]);
        }
        __syncthreads();
        if (tid < 12){
            int which = tid / 6, j = tid % 6;
            const float* v = which ? mx_s : avg_s;
            float h = b1[j];
            for (int c2 = 0; c2 < C; c2++) h = fmaf(v[c2], w1[c2*CH_HID + j], h);
            hid_s[tid] = fmaxf(h, 0.f);
        }
        __syncthreads();
        if (tid < C){
            float z = 2.f * b2[tid];
            for (int j = 0; j < CH_HID; j++)
                z = fmaf(hid_s[j] + hid_s[6+j], w2[j*C + tid], z);
            g_scale[b*C + tid] = 1.f / (1.f + expf(-z));
        }
        __syncthreads();
    }
}

// ---------------- K4: comp = [max_c, mean_c] of x*scale ----------------
__global__ __launch_bounds__(64) void k4_comp(const float* __restrict__ x){
    __shared__ float sc_s[C];
    const int b = blockIdx.y, m = blockIdx.x, z = blockIdx.z, tid = threadIdx.x;
    if (tid < C) sc_s[tid] = g_scale[b*C + tid];
    __syncthreads();

    const int colq = z*64 + tid;          // float4 column index (0..127)
    const float4* base = reinterpret_cast<const float4*>(x) + ((size_t)b*C*PIX + (size_t)m*NS)/4 + colq;
    float4 mx = make_float4(-3.402823466e38f, -3.402823466e38f, -3.402823466e38f, -3.402823466e38f);
    float4 sm = make_float4(0.f, 0.f, 0.f, 0.f);
#pragma unroll 8
    for (int c = 0; c < C; c++){
        float4 v = __ldg(base + (size_t)c*(PIX/4));
        float s = sc_s[c];
        float a = v.x*s, bb = v.y*s, cc = v.z*s, dd = v.w*s;
        mx.x = fmaxf(mx.x, a); mx.y = fmaxf(mx.y, bb); mx.z = fmaxf(mx.z, cc); mx.w = fmaxf(mx.w, dd);
        sm.x += a; sm.y += bb; sm.z += cc; sm.w += dd;
    }
    const float inv = 1.f / 108.f;
    sm.x *= inv; sm.y *= inv; sm.z *= inv; sm.w *= inv;
    const int po = (b*NS + m)*128 + colq;
    reinterpret_cast<float4*>(g_compMax)[po]  = mx;
    reinterpret_cast<float4*>(g_compMean)[po] = sm;
}

// ---------------- K5: 7x7 conv + sigmoid ----------------
#define CT 16
__global__ __launch_bounds__(256) void k5_conv(const float* __restrict__ cw){
    __shared__ float smax[CT+6][CT+6];
    __shared__ float smean[CT+6][CT+6];
    __shared__ float w_s[98];
    const int b = blockIdx.z, m0 = blockIdx.y*CT, n0 = blockIdx.x*CT, tid = threadIdx.x;
    if (tid < 98) w_s[tid] = cw[tid];
    for (int i = tid; i < (CT+6)*(CT+6); i += 256){
        int r = i / (CT+6), cc = i % (CT+6);
        int gm = m0 + r - 3, gn = n0 + cc - 3;
        float a = 0.f, mn = 0.f;
        if (gm >= 0 && gm < NS && gn >= 0 && gn < NS){
            size_t gi = (size_t)(b*NS + gm)*NS + gn;
            a  = g_compMax[gi];
            mn = g_compMean[gi];
        }
        smax[r][cc] = a; smean[r][cc] = mn;
    }
    __syncthreads();
    const int ty = tid / CT, tx = tid % CT;
    float acc = 0.f;
#pragma unroll
    for (int kh = 0; kh < 7; kh++)
#pragma unroll
        for (int kw = 0; kw < 7; kw++){
            acc = fmaf(smax[ty+kh][tx+kw],  w_s[kh*7 + kw],      acc);
            acc = fmaf(smean[ty+kh][tx+kw], w_s[49 + kh*7 + kw], acc);
        }
    acc *= 0.9999950000374997f;
    g_sig[(size_t)(b*NS + m0 + ty)*NS + n0 + tx] = 1.f / (1.f + expf(-acc));
}

// ---------------- K6: final RMW ----------------
__global__ __launch_bounds__(256) void k6_final(float* __restrict__ out, const int* __restrict__ mask){
    const int idx4 = blockIdx.x*256 + threadIdx.x;
    const int nq = idx4 & 127;
    const int m  = (idx4 >> 7) & 511;
    const int bc = idx4 >> 16;
    const int b  = (bc >= C) ? 1 : 0;

    float4 x  = reinterpret_cast<float4*>(out)[idx4];
    const float sc = g_scale[bc];
    float4 sg = reinterpret_cast<const float4*>(g_sig)[(b*NS + m)*128 + nq];

    const int mr = mask[b*NS + m];
    const int n0 = nq*4;
    const int* mcol = mask + b*NS + n0;
    const float NEGINF = __int_as_float(0xff800000);

    float xs[4]  = {x.x, x.y, x.z, x.w};
    float sgv[4] = {sg.x, sg.y, sg.z, sg.w};
    float r[4];
#pragma unroll
    for (int i = 0; i < 4; i++){
        float y = xs[i] * fmaf(sc, sgv[i], 1.f);
        if (m > n0 + i) y -= 1e12f;
        if (mr == 0 || mcol[i] == 0) y = NEGINF;
        r[i] = y * 0.125f;
    }
    reinterpret_cast<float4*>(out)[idx4] = make_float4(r[0], r[1], r[2], r[3]);
}

// ---------------- launcher ----------------
extern "C" void kernel_launch(void* const* d_in, const int* in_sizes, int n_in,
                              void* d_out, int out_size){
    (void)in_sizes; (void)n_in; (void)out_size;
    const float* inputs       = (const float*)d_in[0];
    const float* event_inputs = (const float*)d_in[1];
    const int*   mask         = (const int*)  d_in[2];
    const float* w_dense      = (const float*)d_in[3];
    const float* b_dense      = (const float*)d_in[4];
    const float* w_event      = (const float*)d_in[5];
    const float* b_event      = (const float*)d_in[6];
    const float* mlp_w1       = (const float*)d_in[7];
    const float* mlp_b1       = (const float*)d_in[8];
    const float* mlp_w2       = (const float*)d_in[9];
    const float* mlp_b2       = (const float*)d_in[10];
    const float* conv_w       = (const float*)d_in[11];
    float* out = (float*)d_out;

    k0_init<<<1, 256>>>();
    k1_qk<<<dim3(64, 2), 128>>>(inputs, w_dense, b_dense);
    k1b_ev<<<108, 64>>>(event_inputs, w_event, b_event);
    k_sum<<<4, 64>>>();
    k15_A<<<864, 256>>>();
    k15_Kb<<<256, 256>>>();
    k2_mma<<<dim3(4, 432, 2), 256>>>(out);
    k3_scale<<<1, 128>>>(mlp_w1, mlp_b1, mlp_w2, mlp_b2);
    k4_comp<<<dim3(512, 2, 2), 64>>>(out);
    k5_conv<<<dim3(32, 32, 2), 256>>>(conv_w);
    k6_final<<<55296, 256>>>(out, mask);
}

// round 8
// speedup vs baseline: 1.7250x; 1.0671x over previous
#include <cuda_runtime.h>
#include <cuda_bf16.h>
#include <cstdint>
#include <math.h>

#define B   2
#define NS  512
#define H   768
#define C   108
#define D   64
#define PIX (NS*NS)
#define CH_HID 6
#define MROWS (C*NS)

// ---------------- device scratch ----------------
__device__ float          g_qw[B*NS*D];
__device__ float          g_kw[B*NS*D];
__device__ float          g_ev[C*D];
__device__ float          g_Qs[B*D];
__device__ float          g_Ks[B*D];
__device__ unsigned       g_chanMaxKey[B*C];
__device__ float          g_scale[B*C];
__device__ float          g_compMax[B*PIX];
__device__ float          g_compMean[B*PIX];
__device__ float          g_sig[B*PIX];
__device__ __nv_bfloat16  g_A[B*MROWS*D];     // 14.2 MB: bf16(ev*q)
__device__ __nv_bfloat16  g_Kb[B*NS*D];       // bf16(k)

__device__ __forceinline__ unsigned fkey(float f){
    unsigned u = __float_as_uint(f);
    return (u & 0x80000000u) ? ~u : (u | 0x80000000u);
}
__device__ __forceinline__ float fkeyinv(unsigned k){
    return __uint_as_float((k & 0x80000000u) ? (k & 0x7fffffffu) : ~k);
}
__device__ __forceinline__ uint32_t smem_u32(const void* p){
    uint32_t a;
    asm("{ .reg .u64 t; cvta.to.shared.u64 t, %1; cvt.u32.u64 %0, t; }" : "=r"(a) : "l"(p));
    return a;
}
__device__ __forceinline__ uint32_t swz128(uint32_t off){ return off ^ ((off >> 3) & 0x70); }

// ---- warp-level bf16 tensor core ops (baseline PTX; works on .target sm_100) ----
__device__ __forceinline__ void ldm_x4(uint32_t* r, uint32_t addr){
    asm volatile("ldmatrix.sync.aligned.m8n8.x4.shared.b16 {%0,%1,%2,%3}, [%4];"
        : "=r"(r[0]), "=r"(r[1]), "=r"(r[2]), "=r"(r[3]) : "r"(addr));
}
__device__ __forceinline__ void ldm_x2(uint32_t* r, uint32_t addr){
    asm volatile("ldmatrix.sync.aligned.m8n8.x2.shared.b16 {%0,%1}, [%2];"
        : "=r"(r[0]), "=r"(r[1]) : "r"(addr));
}
__device__ __forceinline__ void mma16816(float* c, const uint32_t* a, const uint32_t* b){
    asm volatile("mma.sync.aligned.m16n8k16.row.col.f32.bf16.bf16.f32 "
        "{%0,%1,%2,%3}, {%4,%5,%6,%7}, {%8,%9}, {%0,%1,%2,%3};"
        : "+f"(c[0]), "+f"(c[1]), "+f"(c[2]), "+f"(c[3])
        : "r"(a[0]), "r"(a[1]), "r"(a[2]), "r"(a[3]), "r"(b[0]), "r"(b[1]));
}

// ---------------- K0 ----------------
__global__ void k0_init(){
    int i = threadIdx.x;
    if (i < B*C) g_chanMaxKey[i] = 0u;
}

// ---------------- K1: dense + RoPE ----------------
#define K1_M 8
__global__ __launch_bounds__(128) void k1_qk(const float* __restrict__ inp,
                                             const float* __restrict__ wd,
                                             const float* __restrict__ bd){
    __shared__ float in_s[K1_M][H];
    __shared__ float seq_s[K1_M][128];
    const int b = blockIdx.y, m0 = blockIdx.x * K1_M, tid = threadIdx.x;

    const float* src = inp + ((size_t)b*NS + m0) * H;
    for (int i = tid; i < K1_M*H; i += 128) in_s[i/H][i%H] = src[i];
    __syncthreads();

    const int col = tid;
    float acc[K1_M];
#pragma unroll
    for (int mi = 0; mi < K1_M; mi++) acc[mi] = 0.f;
#pragma unroll 1
    for (int h = 0; h < H; h += 4){
        float w0 = wd[(h+0)*128 + col];
        float w1 = wd[(h+1)*128 + col];
        float w2 = wd[(h+2)*128 + col];
        float w3 = wd[(h+3)*128 + col];
#pragma unroll
        for (int mi = 0; mi < K1_M; mi++){
            float4 iv = *reinterpret_cast<const float4*>(&in_s[mi][h]);
            acc[mi] = fmaf(iv.x, w0, acc[mi]);
            acc[mi] = fmaf(iv.y, w1, acc[mi]);
            acc[mi] = fmaf(iv.z, w2, acc[mi]);
            acc[mi] = fmaf(iv.w, w3, acc[mi]);
        }
    }
    const float bb = bd[col];
#pragma unroll
    for (int mi = 0; mi < K1_M; mi++) seq_s[mi][col] = acc[mi] + bb;
    __syncthreads();

    for (int t = tid; t < K1_M*64; t += 128){
        int mi = t >> 6, p = t & 63;
        int which = p >> 5, j = p & 31;
        int m = m0 + mi;
        float divf = (float)exp((double)j * -0.28782313662425574);
        float ang  = (float)m * divf;
        double ad  = (double)ang;
        float cv = (float)cos(ad), sv = (float)sin(ad);
        int base = which*64 + 2*j;
        float x0 = seq_s[mi][base], x1 = seq_s[mi][base+1];
        float* dst = which ? g_kw : g_qw;
        size_t o = ((size_t)b*NS + m) * D + 2*j;
        dst[o]   = x0*cv - x1*sv;
        dst[o+1] = x1*cv + x0*sv;
    }
}

// ---------------- K1b: ev ----------------
__global__ __launch_bounds__(64) void k1b_ev(const float* __restrict__ ein,
                                             const float* __restrict__ we,
                                             const float* __restrict__ be){
    __shared__ float e_s[H];
    const int c = blockIdx.x, tid = threadIdx.x;
    for (int i = tid; i < H; i += 64) e_s[i] = ein[(size_t)c*H + i];
    __syncthreads();
    float acc = 0.f;
#pragma unroll 1
    for (int h = 0; h < H; h += 4){
        float4 ev4 = *reinterpret_cast<const float4*>(&e_s[h]);
        acc = fmaf(ev4.x, we[(h+0)*D + tid], acc);
        acc = fmaf(ev4.y, we[(h+1)*D + tid], acc);
        acc = fmaf(ev4.z, we[(h+2)*D + tid], acc);
        acc = fmaf(ev4.w, we[(h+3)*D + tid], acc);
    }
    g_ev[c*D + tid] = acc + be[tid];
}

// ---------------- K_sum2: coalesced column sums ----------------
__global__ __launch_bounds__(256) void k_sum2(){
    __shared__ float red[4][64];
    const int which = blockIdx.x, b = blockIdx.y;
    const int tid = threadIdx.x, d = tid & 63, part = tid >> 6;
    const float* src = (which ? g_kw : g_qw) + (size_t)b*NS*D;
    float s = 0.f;
#pragma unroll 8
    for (int m = part; m < NS; m += 4) s += src[m*64 + d];
    red[part][d] = s;
    __syncthreads();
    if (tid < 64)
        (which ? g_Ks : g_Qs)[b*64 + tid] = red[0][tid] + red[1][tid] + red[2][tid] + red[3][tid];
}

// ---------------- K15a: A = bf16(ev*q) ----------------
__global__ __launch_bounds__(256) void k15_A(){
    __shared__ float ev_s[D];
    const int bid = blockIdx.x;
    const int b = bid / 432, t = bid % 432;
    const int c = t >> 2, m0 = (t & 3) * 128;
    const int tid = threadIdx.x;
    if (tid < D) ev_s[tid] = g_ev[c*D + tid];
    __syncthreads();
    const float* q = g_qw + ((size_t)b*NS + m0)*D;
    __nv_bfloat16* dst = g_A + ((size_t)b*MROWS + (size_t)c*NS + m0)*D;
    for (int i = tid; i < 128*D; i += 256){
        int d = i & 63;
        dst[i] = __float2bfloat16(ev_s[d] * q[i]);
    }
}

// ---------------- K15b: Kb = bf16(kw) ----------------
__global__ __launch_bounds__(256) void k15_Kb(){
    int idx = blockIdx.x*256 + threadIdx.x;
    g_Kb[idx] = __float2bfloat16(g_kw[idx]);
}

// ================= GEMM pass common: tile M=128 (one channel slab) x N=128 =================
// smem: A 16KB @0, B 16KB @16384 (both SW128)
__device__ __forceinline__ void load_tiles_128(char* smem, int b, int c, int m0, int n0, int tid){
    const uint4* pA = reinterpret_cast<const uint4*>(g_A);
    const size_t abase = ((size_t)b*MROWS + (size_t)c*NS + m0) * 8;
    const uint4* pB = reinterpret_cast<const uint4*>(g_Kb);
    const size_t bbase = ((size_t)b*NS + n0) * 8;
#pragma unroll
    for (int it = 0; it < 4; it++){
        int i = it*256 + tid;
        int row = i >> 3, c16 = i & 7;
        uint32_t so = swz128(row*128 + c16*16);
        *reinterpret_cast<uint4*>(smem + so)         = pA[abase + (size_t)row*8 + c16];
        *reinterpret_cast<uint4*>(smem + 16384 + so) = pB[bbase + (size_t)row*8 + c16];
    }
}
__device__ __forceinline__ void mainloop_128(uint32_t sbA, uint32_t sbB, int warp_m, int warp_n,
                                             int lane, float acc[4][4][4]){
#pragma unroll
    for (int kt = 0; kt < 4; kt++){
        uint32_t af[4][4], bf[4][2];
#pragma unroll
        for (int i = 0; i < 4; i++){
            int row = warp_m*64 + i*16 + (lane & 15);
            ldm_x4(af[i], sbA + swz128(row*128 + kt*32 + (lane >> 4)*16));
        }
#pragma unroll
        for (int j = 0; j < 4; j++){
            int row = warp_n*32 + j*8 + (lane & 7);
            ldm_x2(bf[j], sbB + swz128(row*128 + kt*32 + ((lane >> 3) & 1)*16));
        }
#pragma unroll
        for (int i = 0; i < 4; i++)
#pragma unroll
            for (int j = 0; j < 4; j++)
                mma16816(acc[i][j], af[i], bf[j]);
    }
}

// ---------------- KP1: einsum recompute -> per-channel max only ----------------
__global__ __launch_bounds__(256) void kp1_chanmax(){
    __shared__ __align__(1024) char smem[32768];
    __shared__ float red_s[8];
    const uint32_t sbA = smem_u32(smem), sbB = sbA + 16384;
    const int tid = threadIdx.x, wid = tid >> 5, lane = tid & 31;
    const int warp_m = wid >> 2, warp_n = wid & 3;
    const int b = blockIdx.z, rt = blockIdx.y, n0 = blockIdx.x * 128;
    const int c = rt >> 2, m0 = (rt & 3) * 128;

    load_tiles_128(smem, b, c, m0, n0, tid);
    __syncthreads();

    float acc[4][4][4];
#pragma unroll
    for (int i = 0; i < 4; i++)
#pragma unroll
        for (int j = 0; j < 4; j++)
#pragma unroll
            for (int r = 0; r < 4; r++) acc[i][j][r] = 0.f;
    mainloop_128(sbA, sbB, warp_m, warp_n, lane, acc);

    float mx = -3.402823466e38f;
#pragma unroll
    for (int i = 0; i < 4; i++)
#pragma unroll
        for (int j = 0; j < 4; j++)
#pragma unroll
            for (int r = 0; r < 4; r++) mx = fmaxf(mx, acc[i][j][r]);
#pragma unroll
    for (int off = 16; off > 0; off >>= 1)
        mx = fmaxf(mx, __shfl_xor_sync(0xffffffffu, mx, off));
    if (lane == 0) red_s[wid] = mx;
    __syncthreads();
    if (tid == 0){
        float m2 = red_s[0];
#pragma unroll
        for (int w = 1; w < 8; w++) m2 = fmaxf(m2, red_s[w]);
        atomicMax(&g_chanMaxKey[b*C + c], fkey(m2));
    }
}

// ---------------- K3: scale ----------------
__global__ __launch_bounds__(128) void k3_scale(const float* __restrict__ w1, const float* __restrict__ b1,
                                                const float* __restrict__ w2, const float* __restrict__ b2){
    __shared__ float avg_s[C], mx_s[C], hid_s[12];
    const int tid = threadIdx.x;
    for (int b = 0; b < B; b++){
        if (tid < C){
            float s = 0.f;
            for (int d = 0; d < D; d++)
                s = fmaf(g_ev[tid*D + d], g_Qs[b*D + d]*g_Ks[b*D + d], s);
            avg_s[tid] = s * (1.f/262144.f);
            mx_s[tid]  = fkeyinv(g_chanMaxKey[b*C + tid]);
        }
        __syncthreads();
        if (tid < 12){
            int which = tid / 6, j = tid % 6;
            const float* v = which ? mx_s : avg_s;
            float h = b1[j];
            for (int c2 = 0; c2 < C; c2++) h = fmaf(v[c2], w1[c2*CH_HID + j], h);
            hid_s[tid] = fmaxf(h, 0.f);
        }
        __syncthreads();
        if (tid < C){
            float z = 2.f * b2[tid];
            for (int j = 0; j < CH_HID; j++)
                z = fmaf(hid_s[j] + hid_s[6+j], w2[j*C + tid], z);
            g_scale[b*C + tid] = 1.f / (1.f + expf(-z));
        }
        __syncthreads();
    }
}

// ---------------- KP2: einsum recompute over all channels -> comp max/mean per pixel ----------------
// block tile m=32, n=64; 128 thr (4 warps, 2x2), warp tile 16x32; B frags register-resident;
// A (4KB/channel) double-buffered in smem.
__global__ __launch_bounds__(128) void kp2_comp(){
    __shared__ __align__(1024) char smA[2][4096];
    __shared__ __align__(1024) char smB[8192];
    __shared__ float sc_s[C];
    const uint32_t sA0 = smem_u32(smA[0]), sA1 = smem_u32(smA[1]);
    const uint32_t sB  = smem_u32(smB);
    const int tid = threadIdx.x, wid = tid >> 5, lane = tid & 31;
    const int warp_m = wid >> 1, warp_n = wid & 1;
    const int b = blockIdx.z, m0 = blockIdx.y * 32, n0 = blockIdx.x * 64;

    if (tid < C) sc_s[tid] = g_scale[b*C + tid];
    // load B tile (64 rows x 128B)
    {
        const uint4* pB = reinterpret_cast<const uint4*>(g_Kb);
        const size_t bbase = ((size_t)b*NS + n0) * 8;
#pragma unroll
        for (int it = 0; it < 4; it++){
            int i = it*128 + tid;              // 512 uint4
            int row = i >> 3, c16 = i & 7;
            *reinterpret_cast<uint4*>(smB + swz128(row*128 + c16*16)) = pB[bbase + (size_t)row*8 + c16];
        }
    }
    __syncthreads();

    // preload B fragments (fixed across channels)
    uint32_t bf[4][4][2];
#pragma unroll
    for (int kt = 0; kt < 4; kt++)
#pragma unroll
        for (int j = 0; j < 4; j++){
            int row = warp_n*32 + j*8 + (lane & 7);
            ldm_x2(bf[kt][j], sB + swz128(row*128 + kt*32 + ((lane >> 3) & 1)*16));
        }

    const uint4* pA = reinterpret_cast<const uint4*>(g_A);
    const int r0 = tid >> 3, c16a = tid & 7;             // first uint4 this thread loads
    const int r1 = (tid + 128) >> 3;                     // second
    const uint32_t so0 = swz128(r0*128 + c16a*16);
    const uint32_t so1 = swz128(r1*128 + c16a*16);

    // prologue: load channel 0 into buf0
    {
        const size_t abase = ((size_t)b*MROWS + m0) * 8;
        *reinterpret_cast<uint4*>(smA[0] + so0) = pA[abase + (size_t)r0*8 + c16a];
        *reinterpret_cast<uint4*>(smA[0] + so1) = pA[abase + (size_t)r1*8 + c16a];
    }
    __syncthreads();

    float acc[4][4], mx[4][4], sm[4][4];
#pragma unroll
    for (int j = 0; j < 4; j++)
#pragma unroll
        for (int r = 0; r < 4; r++){ acc[j][r] = 0.f; mx[j][r] = -3.402823466e38f; sm[j][r] = 0.f; }

#pragma unroll 1
    for (int c = 0; c < C; c++){
        uint4 pre0, pre1;
        if (c + 1 < C){
            const size_t abase = ((size_t)b*MROWS + (size_t)(c+1)*NS + m0) * 8;
            pre0 = pA[abase + (size_t)r0*8 + c16a];
            pre1 = pA[abase + (size_t)r1*8 + c16a];
        }
        const uint32_t sbA = (c & 1) ? sA1 : sA0;
#pragma unroll
        for (int kt = 0; kt < 4; kt++){
            uint32_t af[4];
            int row = warp_m*16 + (lane & 15);
            ldm_x4(af, sbA + swz128(row*128 + kt*32 + (lane >> 4)*16));
#pragma unroll
            for (int j = 0; j < 4; j++)
                mma16816(acc[j], af, bf[kt][j]);
        }
        const float sc = sc_s[c];
#pragma unroll
        for (int j = 0; j < 4; j++)
#pragma unroll
            for (int r = 0; r < 4; r++){
                float v = acc[j][r] * sc;
                mx[j][r] = fmaxf(mx[j][r], v);
                sm[j][r] += v;
                acc[j][r] = 0.f;
            }
        if (c + 1 < C){
            char* dst = (c & 1) ? smA[0] : smA[1];
            *reinterpret_cast<uint4*>(dst + so0) = pre0;
            *reinterpret_cast<uint4*>(dst + so1) = pre1;
            __syncthreads();
        }
    }

    // write comp tiles
#pragma unroll
    for (int j = 0; j < 4; j++){
        int gm0 = m0 + warp_m*16 + (lane >> 2);
        int gn  = n0 + warp_n*32 + j*8 + (lane & 3)*2;
        size_t p0 = ((size_t)(b*NS + gm0))*NS + gn;
        size_t p1 = ((size_t)(b*NS + gm0 + 8))*NS + gn;
        *reinterpret_cast<float2*>(&g_compMax[p0])  = make_float2(mx[j][0], mx[j][1]);
        *reinterpret_cast<float2*>(&g_compMax[p1])  = make_float2(mx[j][2], mx[j][3]);
        const float inv = 1.f/108.f;
        *reinterpret_cast<float2*>(&g_compMean[p0]) = make_float2(sm[j][0]*inv, sm[j][1]*inv);
        *reinterpret_cast<float2*>(&g_compMean[p1]) = make_float2(sm[j][2]*inv, sm[j][3]*inv);
    }
}

// ---------------- K5: 7x7 conv + sigmoid ----------------
#define CT 16
__global__ __launch_bounds__(256) void k5_conv(const float* __restrict__ cw){
    __shared__ float smax[CT+6][CT+6];
    __shared__ float smean[CT+6][CT+6];
    __shared__ float w_s[98];
    const int b = blockIdx.z, m0 = blockIdx.y*CT, n0 = blockIdx.x*CT, tid = threadIdx.x;
    if (tid < 98) w_s[tid] = cw[tid];
    for (int i = tid; i < (CT+6)*(CT+6); i += 256){
        int r = i / (CT+6), cc = i % (CT+6);
        int gm = m0 + r - 3, gn = n0 + cc - 3;
        float a = 0.f, mn = 0.f;
        if (gm >= 0 && gm < NS && gn >= 0 && gn < NS){
            size_t gi = (size_t)(b*NS + gm)*NS + gn;
            a  = g_compMax[gi];
            mn = g_compMean[gi];
        }
        smax[r][cc] = a; smean[r][cc] = mn;
    }
    __syncthreads();
    const int ty = tid / CT, tx = tid % CT;
    float acc = 0.f;
#pragma unroll
    for (int kh = 0; kh < 7; kh++)
#pragma unroll
        for (int kw = 0; kw < 7; kw++){
            acc = fmaf(smax[ty+kh][tx+kw],  w_s[kh*7 + kw],      acc);
            acc = fmaf(smean[ty+kh][tx+kw], w_s[49 + kh*7 + kw], acc);
        }
    acc *= 0.9999950000374997f;
    g_sig[(size_t)(b*NS + m0 + ty)*NS + n0 + tx] = 1.f / (1.f + expf(-acc));
}

// ---------------- KP3: einsum recompute -> fused final epilogue -> out ----------------
__global__ __launch_bounds__(256) void kp3_final(float* __restrict__ out, const int* __restrict__ mask){
    __shared__ __align__(1024) char smem[32768];
    __shared__ int mrow_s[128], mcol_s[128];
    const uint32_t sbA = smem_u32(smem), sbB = sbA + 16384;
    const int tid = threadIdx.x, wid = tid >> 5, lane = tid & 31;
    const int warp_m = wid >> 2, warp_n = wid & 3;
    const int b = blockIdx.z, rt = blockIdx.y, n0 = blockIdx.x * 128;
    const int c = rt >> 2, m0 = (rt & 3) * 128;

    load_tiles_128(smem, b, c, m0, n0, tid);
    if (tid < 128){
        mrow_s[tid] = mask[b*NS + m0 + tid];
        mcol_s[tid] = mask[b*NS + n0 + tid];
    }
    __syncthreads();

    float acc[4][4][4];
#pragma unroll
    for (int i = 0; i < 4; i++)
#pragma unroll
        for (int j = 0; j < 4; j++)
#pragma unroll
            for (int r = 0; r < 4; r++) acc[i][j][r] = 0.f;
    mainloop_128(sbA, sbB, warp_m, warp_n, lane, acc);

    const float sc = g_scale[b*C + c];
    const size_t obase = ((size_t)(b*C + c)*NS + m0)*NS + n0;
    const float NEGINF = __int_as_float(0xff800000);
#pragma unroll
    for (int i = 0; i < 4; i++){
        int lrow0 = warp_m*64 + i*16 + (lane >> 2);
#pragma unroll
        for (int j = 0; j < 4; j++){
            int lcol = warp_n*32 + j*8 + (lane & 3)*2;
            int gn = n0 + lcol;
            int mc0 = mcol_s[lcol], mc1 = mcol_s[lcol+1];
#pragma unroll
            for (int h = 0; h < 2; h++){
                int lrow = lrow0 + h*8;
                int gm = m0 + lrow;
                float2 sg = *reinterpret_cast<const float2*>(&g_sig[((size_t)(b*NS + gm))*NS + gn]);
                int mr = mrow_s[lrow];
                float y0 = acc[i][j][2*h]   * fmaf(sc, sg.x, 1.f);
                float y1 = acc[i][j][2*h+1] * fmaf(sc, sg.y, 1.f);
                if (gm > gn)     y0 -= 1e12f;
                if (gm > gn + 1) y1 -= 1e12f;
                if (mr == 0 || mc0 == 0) y0 = NEGINF;
                if (mr == 0 || mc1 == 0) y1 = NEGINF;
                *reinterpret_cast<float2*>(&out[obase + (size_t)lrow*NS + lcol]) =
                    make_float2(y0 * 0.125f, y1 * 0.125f);
            }
        }
    }
}

// ---------------- launcher ----------------
extern "C" void kernel_launch(void* const* d_in, const int* in_sizes, int n_in,
                              void* d_out, int out_size){
    (void)in_sizes; (void)n_in; (void)out_size;
    const float* inputs       = (const float*)d_in[0];
    const float* event_inputs = (const float*)d_in[1];
    const int*   mask         = (const int*)  d_in[2];
    const float* w_dense      = (const float*)d_in[3];
    const float* b_dense      = (const float*)d_in[4];
    const float* w_event      = (const float*)d_in[5];
    const float* b_event      = (const float*)d_in[6];
    const float* mlp_w1       = (const float*)d_in[7];
    const float* mlp_b1       = (const float*)d_in[8];
    const float* mlp_w2       = (const float*)d_in[9];
    const float* mlp_b2       = (const float*)d_in[10];
    const float* conv_w       = (const float*)d_in[11];
    float* out = (float*)d_out;

    k0_init<<<1, 256>>>();
    k1_qk<<<dim3(64, 2), 128>>>(inputs, w_dense, b_dense);
    k1b_ev<<<108, 64>>>(event_inputs, w_event, b_event);
    k_sum2<<<dim3(2, 2), 256>>>();
    k15_A<<<864, 256>>>();
    k15_Kb<<<256, 256>>>();
    kp1_chanmax<<<dim3(4, 432, 2), 256>>>();
    k3_scale<<<1, 128>>>(mlp_w1, mlp_b1, mlp_w2, mlp_b2);
    kp2_comp<<<dim3(8, 16, 2), 128>>>();
    k5_conv<<<dim3(32, 32, 2), 256>>>(conv_w);
    kp3_final<<<dim3(4, 432, 2), 256>>>(out, mask);
}